// round 2
// baseline (speedup 1.0000x reference)
#include <cuda_runtime.h>
#include <math.h>

#define TT   4096
#define HD   512
#define NC   4880
#define G3   1536
#define NBLK 32

// ---------------- scratch (static device globals; no allocation) ----------------
__device__ float g_visit[(size_t)TT * HD];          // 8 MB
__device__ float g_gi[(size_t)TT * G3];             // 24 MB
__device__ float g_hs[(size_t)TT * HD];             // 8 MB
__device__ __align__(16) float g_hbuf[2][HD];       // double-buffered hidden state
__device__ unsigned g_bar;                          // grid barrier counter
__device__ float g_logits[TT];
__device__ float g_alpha[TT];
__device__ float g_part[64 * HD];

// ---------------- Phase 1: visit_emb = H^T @ X_emb  (4096x512, K=4880) ----------
// C[t][v] = sum_c H[c][t] * X[c][v]
__global__ void k_visit(const float* __restrict__ H, const float* __restrict__ X) {
    __shared__ float4 sH[16][16];   // [k][t/4]
    __shared__ float4 sX[16][16];   // [k][v/4]
    const int tid = threadIdx.x;          // 256 threads
    const int lk = tid >> 4, lx = tid & 15;
    const int cy = tid >> 4, cx = tid & 15;
    const int t0 = blockIdx.y << 6, v0 = blockIdx.x << 6;

    float acc[4][4];
#pragma unroll
    for (int i = 0; i < 4; i++)
#pragma unroll
        for (int j = 0; j < 4; j++) acc[i][j] = 0.f;

    for (int c0 = 0; c0 < NC; c0 += 16) {
        sH[lk][lx] = *(const float4*)(H + (size_t)(c0 + lk) * TT + t0 + (lx << 2));
        sX[lk][lx] = *(const float4*)(X + (size_t)(c0 + lk) * HD + v0 + (lx << 2));
        __syncthreads();
#pragma unroll
        for (int k = 0; k < 16; k++) {
            float4 a = sH[k][cy];
            float4 b = sX[k][cx];
            float av[4] = {a.x, a.y, a.z, a.w};
            float bv[4] = {b.x, b.y, b.z, b.w};
#pragma unroll
            for (int i = 0; i < 4; i++)
#pragma unroll
                for (int j = 0; j < 4; j++) acc[i][j] += av[i] * bv[j];
        }
        __syncthreads();
    }
#pragma unroll
    for (int i = 0; i < 4; i++) {
        float4 o = make_float4(acc[i][0], acc[i][1], acc[i][2], acc[i][3]);
        *(float4*)&g_visit[(size_t)(t0 + (cy << 2) + i) * HD + v0 + (cx << 2)] = o;
    }
}

// ---------------- Phase 2: gi = visit_emb @ W_ih^T + b_ih  (4096x1536, K=512) ---
// C[t][r] = sum_k V[t][k] * W[r][k] + b[r]
__global__ void k_gi(const float* __restrict__ W, const float* __restrict__ bih) {
    __shared__ float sA[16][68];   // [k][t]
    __shared__ float sB[16][68];   // [k][r]
    const int tid = threadIdx.x;         // 256 threads
    const int lr = tid >> 2, lk = (tid & 3) << 2;
    const int cy = tid >> 4, cx = tid & 15;
    const int t0 = blockIdx.y << 6, r0 = blockIdx.x << 6;

    float acc[4][4];
#pragma unroll
    for (int i = 0; i < 4; i++)
#pragma unroll
        for (int j = 0; j < 4; j++) acc[i][j] = 0.f;

    for (int k0 = 0; k0 < HD; k0 += 16) {
        float4 a = *(const float4*)(g_visit + (size_t)(t0 + lr) * HD + k0 + lk);
        float4 w = *(const float4*)(W + (size_t)(r0 + lr) * HD + k0 + lk);
        sA[lk + 0][lr] = a.x; sA[lk + 1][lr] = a.y; sA[lk + 2][lr] = a.z; sA[lk + 3][lr] = a.w;
        sB[lk + 0][lr] = w.x; sB[lk + 1][lr] = w.y; sB[lk + 2][lr] = w.z; sB[lk + 3][lr] = w.w;
        __syncthreads();
#pragma unroll
        for (int k = 0; k < 16; k++) {
            float av[4], bv[4];
#pragma unroll
            for (int i = 0; i < 4; i++) av[i] = sA[k][(cy << 2) + i];
#pragma unroll
            for (int j = 0; j < 4; j++) bv[j] = sB[k][(cx << 2) + j];
#pragma unroll
            for (int i = 0; i < 4; i++)
#pragma unroll
                for (int j = 0; j < 4; j++) acc[i][j] += av[i] * bv[j];
        }
        __syncthreads();
    }
    const float4 bb = *(const float4*)&bih[r0 + (cx << 2)];
    float bv[4] = {bb.x, bb.y, bb.z, bb.w};
#pragma unroll
    for (int i = 0; i < 4; i++) {
        float4 o = make_float4(acc[i][0] + bv[0], acc[i][1] + bv[1],
                               acc[i][2] + bv[2], acc[i][3] + bv[3]);
        *(float4*)&g_gi[(size_t)(t0 + (cy << 2) + i) * G3 + r0 + (cx << 2)] = o;
    }
}

// ---------------- Phase 3: sequential GRU scan, persistent 32-block kernel ------
// Block b owns h indices j in [16b, 16b+16). Warp w handles j = 16b + w, i.e.
// W_hh rows {j, 512+j, 1024+j}; lane l holds weights for columns k = l + 32m,
// m = 0..15 (register resident: 48 floats/lane).
__global__ void __launch_bounds__(512, 1) k_scan(const float* __restrict__ Whh,
                                                 const float* __restrict__ bhh) {
    const int b = blockIdx.x, tid = threadIdx.x;
    const int w = tid >> 5, l = tid & 31;
    const int j = (b << 4) + w;

    float wr[16], wz[16], wn[16];
    const float* Wr = Whh + (size_t)j * HD;
    const float* Wz = Whh + (size_t)(HD + j) * HD;
    const float* Wn = Whh + (size_t)(2 * HD + j) * HD;
#pragma unroll
    for (int m = 0; m < 16; m++) {
        int k = l + (m << 5);
        wr[m] = Wr[k]; wz[m] = Wz[k]; wn[m] = Wn[k];
    }
    const float br = bhh[j], bz = bhh[HD + j], bn = bhh[2 * HD + j];

    __shared__ __align__(16) float sh[HD];
    volatile unsigned* barp = &g_bar;

    for (int t = 0; t < TT; t++) {
        // prefetch this step's input-gate values (independent of h)
        float ir = 0.f, iz = 0.f, in_ = 0.f;
        if (l == 0) {
            const float* g = g_gi + (size_t)t * G3;
            ir  = g[j];
            iz  = g[HD + j];
            in_ = g[2 * HD + j];
        }
        // wait until all blocks finished step t-1 (their arrivals follow their
        // h-reads and h-writes, so g_hbuf[t&1] is complete and buffer reuse safe)
        if (tid == 0) {
            const unsigned tgt = (unsigned)t * NBLK;
            while (*barp < tgt) {}
            __threadfence();   // acquire
        }
        __syncthreads();
        // stage current h into SMEM (bypass L1: written by other SMs)
        if (tid < 128)
            ((float4*)sh)[tid] = __ldcg(((const float4*)g_hbuf[t & 1]) + tid);
        __syncthreads();

        float ar = 0.f, az = 0.f, an = 0.f;
#pragma unroll
        for (int m = 0; m < 16; m++) {
            float hv = sh[l + (m << 5)];
            ar += wr[m] * hv;
            az += wz[m] * hv;
            an += wn[m] * hv;
        }
#pragma unroll
        for (int o = 16; o; o >>= 1) {
            ar += __shfl_down_sync(0xffffffffu, ar, o);
            az += __shfl_down_sync(0xffffffffu, az, o);
            an += __shfl_down_sync(0xffffffffu, an, o);
        }
        if (l == 0) {
            float r  = 1.f / (1.f + expf(-(ir + ar + br)));
            float z  = 1.f / (1.f + expf(-(iz + az + bz)));
            float n  = tanhf(in_ + r * (an + bn));
            float hn = (1.f - z) * n + z * sh[j];
            g_hbuf[(t & 1) ^ 1][j]   = hn;
            g_hs[(size_t)t * HD + j] = hn;
        }
        __syncthreads();
        if (tid == 0) {
            __threadfence();   // release our block's h writes
            atomicAdd(&g_bar, 1u);
        }
    }
}

// ---------------- Phase 4: attention pooling ------------------------------------
__global__ void k_logits(const float* __restrict__ watt) {
    const int wp = threadIdx.x >> 5, l = threadIdx.x & 31;
    const int t = (blockIdx.x << 3) + wp;
    const float* hr = g_hs + (size_t)t * HD;
    float s = 0.f;
#pragma unroll
    for (int m = 0; m < 16; m++) {
        int k = l + (m << 5);
        s += hr[k] * watt[k];
    }
#pragma unroll
    for (int o = 16; o; o >>= 1) s += __shfl_down_sync(0xffffffffu, s, o);
    if (l == 0) g_logits[t] = s;
}

__global__ void k_softmax() {
    __shared__ float sred[16];
    const int tid = threadIdx.x;   // 512 threads, 8 logits each
    float v[8];
    float mx = -3.402823466e38f;
#pragma unroll
    for (int i = 0; i < 8; i++) {
        v[i] = g_logits[tid + (i << 9)];
        mx = fmaxf(mx, v[i]);
    }
#pragma unroll
    for (int o = 16; o; o >>= 1) mx = fmaxf(mx, __shfl_xor_sync(0xffffffffu, mx, o));
    if ((tid & 31) == 0) sred[tid >> 5] = mx;
    __syncthreads();
    if (tid == 0) {
        float m = sred[0];
        for (int i = 1; i < 16; i++) m = fmaxf(m, sred[i]);
        sred[0] = m;
    }
    __syncthreads();
    const float m = sred[0];
    __syncthreads();
    float s = 0.f;
#pragma unroll
    for (int i = 0; i < 8; i++) {
        v[i] = expf(v[i] - m);
        s += v[i];
    }
#pragma unroll
    for (int o = 16; o; o >>= 1) s += __shfl_xor_sync(0xffffffffu, s, o);
    if ((tid & 31) == 0) sred[tid >> 5] = s;
    __syncthreads();
    if (tid == 0) {
        float S = 0.f;
        for (int i = 0; i < 16; i++) S += sred[i];
        sred[0] = S;
    }
    __syncthreads();
    const float inv = 1.f / sred[0];
#pragma unroll
    for (int i = 0; i < 8; i++) g_alpha[tid + (i << 9)] = v[i] * inv;
}

__global__ void k_wsum() {
    const int j = threadIdx.x, b = blockIdx.x;   // 64 blocks x 512 threads
    float acc = 0.f;
    const int t0 = b << 6;
    for (int t = t0; t < t0 + 64; t++)
        acc += g_alpha[t] * g_hs[(size_t)t * HD + j];
    g_part[b * HD + j] = acc;
}

__global__ void k_final(float* __restrict__ out) {
    const int j = threadIdx.x;
    float a = 0.f;
    for (int b = 0; b < 64; b++) a += g_part[b * HD + j];
    out[j] = a;
}

// ---------------- launch --------------------------------------------------------
extern "C" void kernel_launch(void* const* d_in, const int* in_sizes, int n_in,
                              void* d_out, int out_size) {
    const float* H    = (const float*)d_in[0];
    // d_in[1] = TE (unused by reference)
    const float* X    = (const float*)d_in[2];
    const float* Wih  = (const float*)d_in[3];
    const float* Whh  = (const float*)d_in[4];
    const float* bih  = (const float*)d_in[5];
    const float* bhh  = (const float*)d_in[6];
    const float* watt = (const float*)d_in[7];
    float* out = (float*)d_out;

    void* pbar = 0;
    void* phb  = 0;
    cudaGetSymbolAddress(&pbar, g_bar);
    cudaGetSymbolAddress(&phb, g_hbuf);
    cudaMemsetAsync(pbar, 0, sizeof(unsigned));              // reset barrier
    cudaMemsetAsync(phb, 0, 2 * HD * sizeof(float));         // h0 = 0

    k_visit<<<dim3(HD / 64, TT / 64), 256>>>(H, X);
    k_gi<<<dim3(G3 / 64, TT / 64), 256>>>(Wih, bih);
    k_scan<<<NBLK, 512>>>(Whh, bhh);
    k_logits<<<TT / 8, 256>>>(watt);
    k_softmax<<<1, 512>>>();
    k_wsum<<<64, 512>>>();
    k_final<<<1, 512>>>(out);
}

// round 6
// speedup vs baseline: 1.0502x; 1.0502x over previous
#include <cuda_runtime.h>
#include <math.h>

#define TT   4096
#define HD   512
#define NC   4880
#define G3   1536
#define SNB  64      // scan CTAs (1 output per warp, 8 per CTA)

// ---------------- scratch (static device globals; no allocation) ----------------
__device__ float g_visit[(size_t)TT * HD];          // 8 MB
__device__ float g_gi[(size_t)TT * G3];             // 24 MB
__device__ float g_hs[(size_t)TT * HD];             // 8 MB; also the h delivery path
__device__ unsigned g_bar;                          // grid barrier counter
__device__ float g_logits[TT];
__device__ float g_alpha[TT];
__device__ float g_part[64 * HD];

// ---------------- Phase 1: visit_emb = H^T @ X_emb  (4096x512, K=4880) ----------
// C[t][v] = sum_c H[c][t] * X[c][v].  128x128 tile, 8x8 per thread, kb=8.
// Summation order over c is identical to the proven R2 kernel -> bitwise-equal.
__global__ void __launch_bounds__(256) k_visit(const float* __restrict__ H,
                                               const float* __restrict__ X) {
    __shared__ float sA[8][132];   // [k][t]
    __shared__ float sB[8][132];   // [k][v]
    const int tid = threadIdx.x;
    const int t0 = blockIdx.y << 7, v0 = blockIdx.x << 7;
    const int lk = tid >> 5;            // 0..7
    const int lc = (tid & 31) << 2;     // 0..124
    const int ty = tid >> 4;            // 0..15
    const int tx = tid & 15;

    float acc[8][8];
#pragma unroll
    for (int i = 0; i < 8; i++)
#pragma unroll
        for (int jj = 0; jj < 8; jj++) acc[i][jj] = 0.f;

    const float* pa = H + (size_t)lk * TT + t0 + lc;
    const float* pb = X + (size_t)lk * HD + v0 + lc;
    float4 an = *(const float4*)pa;
    float4 bn = *(const float4*)pb;

    for (int c0 = 0; c0 < NC; c0 += 8) {
        *(float4*)&sA[lk][lc] = an;
        *(float4*)&sB[lk][lc] = bn;
        __syncthreads();
        if (c0 + 8 < NC) {
            pa += (size_t)8 * TT;
            pb += (size_t)8 * HD;
            an = *(const float4*)pa;
            bn = *(const float4*)pb;
        }
#pragma unroll
        for (int k = 0; k < 8; k++) {
            float a[8], b[8];
            float4 a0 = *(const float4*)&sA[k][ty << 2];
            float4 a1 = *(const float4*)&sA[k][(ty << 2) + 64];
            float4 b0 = *(const float4*)&sB[k][tx << 2];
            float4 b1 = *(const float4*)&sB[k][(tx << 2) + 64];
            a[0]=a0.x; a[1]=a0.y; a[2]=a0.z; a[3]=a0.w;
            a[4]=a1.x; a[5]=a1.y; a[6]=a1.z; a[7]=a1.w;
            b[0]=b0.x; b[1]=b0.y; b[2]=b0.z; b[3]=b0.w;
            b[4]=b1.x; b[5]=b1.y; b[6]=b1.z; b[7]=b1.w;
#pragma unroll
            for (int i = 0; i < 8; i++)
#pragma unroll
                for (int jj = 0; jj < 8; jj++) acc[i][jj] += a[i] * b[jj];
        }
        __syncthreads();
    }
#pragma unroll
    for (int i = 0; i < 8; i++) {
        int row = t0 + (ty << 2) + (i & 3) + ((i >= 4) ? 64 : 0);
        float4 o0 = make_float4(acc[i][0], acc[i][1], acc[i][2], acc[i][3]);
        float4 o1 = make_float4(acc[i][4], acc[i][5], acc[i][6], acc[i][7]);
        *(float4*)&g_visit[(size_t)row * HD + v0 + (tx << 2)]      = o0;
        *(float4*)&g_visit[(size_t)row * HD + v0 + (tx << 2) + 64] = o1;
    }
}

// ---------------- Phase 2: gi = visit_emb @ W_ih^T + b_ih  (4096x1536, K=512) ---
__global__ void k_gi(const float* __restrict__ W, const float* __restrict__ bih) {
    __shared__ float sA[16][68];   // [k][t]
    __shared__ float sB[16][68];   // [k][r]
    const int tid = threadIdx.x;         // 256 threads
    const int lr = tid >> 2, lk = (tid & 3) << 2;
    const int cy = tid >> 4, cx = tid & 15;
    const int t0 = blockIdx.y << 6, r0 = blockIdx.x << 6;

    float acc[4][4];
#pragma unroll
    for (int i = 0; i < 4; i++)
#pragma unroll
        for (int j = 0; j < 4; j++) acc[i][j] = 0.f;

    for (int k0 = 0; k0 < HD; k0 += 16) {
        float4 a = *(const float4*)(g_visit + (size_t)(t0 + lr) * HD + k0 + lk);
        float4 w = *(const float4*)(W + (size_t)(r0 + lr) * HD + k0 + lk);
        sA[lk + 0][lr] = a.x; sA[lk + 1][lr] = a.y; sA[lk + 2][lr] = a.z; sA[lk + 3][lr] = a.w;
        sB[lk + 0][lr] = w.x; sB[lk + 1][lr] = w.y; sB[lk + 2][lr] = w.z; sB[lk + 3][lr] = w.w;
        __syncthreads();
#pragma unroll
        for (int k = 0; k < 16; k++) {
            float av[4], bv[4];
#pragma unroll
            for (int i = 0; i < 4; i++) av[i] = sA[k][(cy << 2) + i];
#pragma unroll
            for (int j = 0; j < 4; j++) bv[j] = sB[k][(cx << 2) + j];
#pragma unroll
            for (int i = 0; i < 4; i++)
#pragma unroll
                for (int j = 0; j < 4; j++) acc[i][j] += av[i] * bv[j];
        }
        __syncthreads();
    }
    const float4 bb = *(const float4*)&bih[r0 + (cx << 2)];
    float bv[4] = {bb.x, bb.y, bb.z, bb.w};
#pragma unroll
    for (int i = 0; i < 4; i++) {
        float4 o = make_float4(acc[i][0] + bv[0], acc[i][1] + bv[1],
                               acc[i][2] + bv[2], acc[i][3] + bv[3]);
        *(float4*)&g_gi[(size_t)(t0 + (cy << 2) + i) * G3 + r0 + (cx << 2)] = o;
    }
}

// ---------------- Phase 3: sequential GRU scan, R2-proven barrier protocol ------
// 64 CTAs x 256 threads. Warp w of CTA b owns output j = 8b + w; W_hh rows
// {j, 512+j, 1024+j} register resident (48 floats/lane).
// Sync protocol is EXACTLY the proven R2 one: per step, each CTA's thread 0
// spins on the volatile counter until all CTAs arrived for step t-1 (arrivals
// are release-fenced AFTER the h stores; the spin is followed by an acquire
// fence; bar.sync edges make the pattern cumulative per the PTX model).
// h delivery: h(t-1) is read from g_hs row t-1 via __ldcg (L1-bypassing).
// Rows are written once and never reused -> no write-after-read hazard at all.
__global__ void __launch_bounds__(256, 1) k_scan(const float* __restrict__ Whh,
                                                 const float* __restrict__ bhh) {
    const int b = blockIdx.x, tid = threadIdx.x;
    const int w = tid >> 5, l = tid & 31;
    const int j = (b << 3) + w;

    float wr[16], wz[16], wn[16];
    const float* Wr = Whh + (size_t)j * HD;
    const float* Wz = Whh + (size_t)(HD + j) * HD;
    const float* Wn = Whh + (size_t)(2 * HD + j) * HD;
#pragma unroll
    for (int m = 0; m < 16; m++) {
        int k = l + (m << 5);
        wr[m] = Wr[k]; wz[m] = Wz[k]; wn[m] = Wn[k];
    }
    const float br = bhh[j], bz = bhh[HD + j], bnn = bhh[2 * HD + j];

    __shared__ __align__(16) float sh[HD];
    volatile unsigned* barp = &g_bar;

    for (int t = 0; t < TT; t++) {
        // prefetch input-gate values (independent of h; overlaps the spin)
        float ir = 0.f, iz = 0.f, in_ = 0.f;
        if (l == 0) {
            const float* g = g_gi + (size_t)t * G3;
            ir  = g[j];
            iz  = g[HD + j];
            in_ = g[2 * HD + j];
        }
        // wait until all CTAs finished step t-1 (their arrivals are release-
        // fenced after their g_hs row t-1 stores)
        if (tid == 0 && t > 0) {
            const unsigned tgt = (unsigned)t * SNB;
            while (*barp < tgt) {}
            __threadfence();   // acquire
        }
        __syncthreads();
        // stage h(t-1) into SMEM (L2 read; L1 may be stale across SMs)
        if (tid < 128) {
            if (t == 0)
                ((float4*)sh)[tid] = make_float4(0.f, 0.f, 0.f, 0.f);
            else
                ((float4*)sh)[tid] =
                    __ldcg(((const float4*)(g_hs + (size_t)(t - 1) * HD)) + tid);
        }
        __syncthreads();

        float ar = 0.f, az = 0.f, an = 0.f;
#pragma unroll
        for (int m = 0; m < 16; m++) {
            float hv = sh[l + (m << 5)];
            ar += wr[m] * hv;
            az += wz[m] * hv;
            an += wn[m] * hv;
        }
#pragma unroll
        for (int o = 16; o; o >>= 1) {
            ar += __shfl_down_sync(0xffffffffu, ar, o);
            az += __shfl_down_sync(0xffffffffu, az, o);
            an += __shfl_down_sync(0xffffffffu, an, o);
        }
        if (l == 0) {
            float r  = 1.f / (1.f + expf(-(ir + ar + br)));
            float z  = 1.f / (1.f + expf(-(iz + az + bz)));
            float n  = tanhf(in_ + r * (an + bnn));
            float hn = (1.f - z) * n + z * sh[j];
            g_hs[(size_t)t * HD + j] = hn;
        }
        __syncthreads();
        if (tid == 0) {
            __threadfence();        // release our CTA's h stores
            atomicAdd(&g_bar, 1u);
        }
    }
}

// ---------------- Phase 4: attention pooling ------------------------------------
__global__ void k_logits(const float* __restrict__ watt) {
    const int wp = threadIdx.x >> 5, l = threadIdx.x & 31;
    const int t = (blockIdx.x << 3) + wp;
    const float* hr = g_hs + (size_t)t * HD;
    float s = 0.f;
#pragma unroll
    for (int m = 0; m < 16; m++) {
        int k = l + (m << 5);
        s += hr[k] * watt[k];
    }
#pragma unroll
    for (int o = 16; o; o >>= 1) s += __shfl_down_sync(0xffffffffu, s, o);
    if (l == 0) g_logits[t] = s;
}

__global__ void k_softmax() {
    __shared__ float sred[16];
    const int tid = threadIdx.x;   // 512 threads, 8 logits each
    float v[8];
    float mx = -3.402823466e38f;
#pragma unroll
    for (int i = 0; i < 8; i++) {
        v[i] = g_logits[tid + (i << 9)];
        mx = fmaxf(mx, v[i]);
    }
#pragma unroll
    for (int o = 16; o; o >>= 1) mx = fmaxf(mx, __shfl_xor_sync(0xffffffffu, mx, o));
    if ((tid & 31) == 0) sred[tid >> 5] = mx;
    __syncthreads();
    if (tid == 0) {
        float m = sred[0];
        for (int i = 1; i < 16; i++) m = fmaxf(m, sred[i]);
        sred[0] = m;
    }
    __syncthreads();
    const float m = sred[0];
    __syncthreads();
    float s = 0.f;
#pragma unroll
    for (int i = 0; i < 8; i++) {
        v[i] = expf(v[i] - m);
        s += v[i];
    }
#pragma unroll
    for (int o = 16; o; o >>= 1) s += __shfl_xor_sync(0xffffffffu, s, o);
    if ((tid & 31) == 0) sred[tid >> 5] = s;
    __syncthreads();
    if (tid == 0) {
        float S = 0.f;
        for (int i = 0; i < 16; i++) S += sred[i];
        sred[0] = S;
    }
    __syncthreads();
    const float inv = 1.f / sred[0];
#pragma unroll
    for (int i = 0; i < 8; i++) g_alpha[tid + (i << 9)] = v[i] * inv;
}

__global__ void k_wsum() {
    const int j = threadIdx.x, b = blockIdx.x;   // 64 blocks x 512 threads
    float acc = 0.f;
    const int t0 = b << 6;
    for (int t = t0; t < t0 + 64; t++)
        acc += g_alpha[t] * g_hs[(size_t)t * HD + j];
    g_part[b * HD + j] = acc;
}

__global__ void k_final(float* __restrict__ out) {
    const int j = threadIdx.x;
    float a = 0.f;
    for (int b = 0; b < 64; b++) a += g_part[b * HD + j];
    out[j] = a;
}

// ---------------- launch --------------------------------------------------------
extern "C" void kernel_launch(void* const* d_in, const int* in_sizes, int n_in,
                              void* d_out, int out_size) {
    const float* H    = (const float*)d_in[0];
    // d_in[1] = TE (unused by reference)
    const float* X    = (const float*)d_in[2];
    const float* Wih  = (const float*)d_in[3];
    const float* Whh  = (const float*)d_in[4];
    const float* bih  = (const float*)d_in[5];
    const float* bhh  = (const float*)d_in[6];
    const float* watt = (const float*)d_in[7];
    float* out = (float*)d_out;

    void* pbar = 0;
    cudaGetSymbolAddress(&pbar, g_bar);
    cudaMemsetAsync(pbar, 0, sizeof(unsigned));   // reset barrier each launch

    k_visit<<<dim3(HD / 128, TT / 128), 256>>>(H, X);
    k_gi<<<dim3(G3 / 64, TT / 64), 256>>>(Wih, bih);
    k_scan<<<SNB, 256>>>(Whh, bhh);
    k_logits<<<TT / 8, 256>>>(watt);
    k_softmax<<<1, 512>>>();
    k_wsum<<<64, 512>>>();
    k_final<<<1, 512>>>(out);
}